// round 3
// baseline (speedup 1.0000x reference)
#include <cuda_runtime.h>
#include <cstddef>

#define EMB_E   300
#define HID     128
#define NT      12
#define SOS_T   3
#define EOS_T   4
#define NEGV    (-10000.0f)
#define BATCH   128
#define SEQ     512
#define G4H     512

// Scratch (device globals; no runtime allocation allowed)
__device__ float g_WX[67108864];   // [dir][b][s][512] input proj + bias
__device__ float g_H [16777216];   // [dir][b][s][128] hidden states

// ---------------------------------------------------------------------------
// K1: fused embedding gather + input GEMM (+bias), both directions.
// Grid 512 CTAs (128-row M tile), 256 threads. Loops 8 N-tiles of 128.
// ---------------------------------------------------------------------------
__global__ void __launch_bounds__(256) input_gemm_kernel(
    const int* __restrict__ x, const float* __restrict__ embed,
    const float* __restrict__ Wih_f, const float* __restrict__ b_f,
    const float* __restrict__ Wih_b, const float* __restrict__ b_b)
{
    extern __shared__ float sm[];
    float* As = sm;                          // 304*128, k-major
    float* Bs = sm + 304 * 128;              // 16*132
    int*   xs = (int*)(sm + 304 * 128 + 16 * 132);

    const int tid = threadIdx.x;
    const int m0  = blockIdx.x * 128;

    if (tid < 128) xs[tid] = x[m0 + tid];
    __syncthreads();

    {   // A tile: 128 gathered rows, K padded 300 -> 304
        const int m  = tid & 127;
        const int kh = tid >> 7;             // 0/1, each half covers 152 k
        const float* row = embed + (size_t)xs[m] * EMB_E + kh * 152;
        #pragma unroll
        for (int i = 0; i < 38; i++) {
            const int k = kh * 152 + i * 4;
            float4 v = (k < 300) ? *(const float4*)(row + i * 4)
                                 : make_float4(0.f, 0.f, 0.f, 0.f);
            As[(k + 0) * 128 + m] = v.x;
            As[(k + 1) * 128 + m] = v.y;
            As[(k + 2) * 128 + m] = v.z;
            As[(k + 3) * 128 + m] = v.w;
        }
    }

    const int tx = tid & 15;
    const int ty = tid >> 4;

    for (int nt = 0; nt < 8; nt++) {
        const int dir   = nt >> 2;
        const int ncol0 = (nt & 3) * 128;
        const float* Wsrc = dir ? Wih_b : Wih_f;
        const float* bsrc = dir ? b_b   : b_f;

        float acc[8][8];
        #pragma unroll
        for (int i = 0; i < 8; i++)
            #pragma unroll
            for (int j = 0; j < 8; j++) acc[i][j] = 0.f;

        for (int k0 = 0; k0 < 304; k0 += 16) {
            __syncthreads();
            {   // B chunk: Bs[kk][n] = W[ncol0+n][k0+kk]
                const int n   = tid & 127;
                const int kk0 = (tid >> 7) * 8;
                const float* wrow = Wsrc + (size_t)(ncol0 + n) * EMB_E;
                #pragma unroll
                for (int q = 0; q < 8; q++) {
                    const int k = k0 + kk0 + q;
                    Bs[(kk0 + q) * 132 + n] = (k < 300) ? wrow[k] : 0.f;
                }
            }
            __syncthreads();

            #pragma unroll
            for (int kk = 0; kk < 16; kk++) {
                float a[8], bb[8];
                const float* ap = As + (k0 + kk) * 128 + ty * 8;
                const float* bp = Bs + kk * 132 + tx * 8;
                *(float4*)(a)      = *(const float4*)(ap);
                *(float4*)(a + 4)  = *(const float4*)(ap + 4);
                *(float4*)(bb)     = *(const float4*)(bp);
                *(float4*)(bb + 4) = *(const float4*)(bp + 4);
                #pragma unroll
                for (int i = 0; i < 8; i++)
                    #pragma unroll
                    for (int j = 0; j < 8; j++)
                        acc[i][j] += a[i] * bb[j];
            }
        }

        float bias[8];
        #pragma unroll
        for (int j = 0; j < 8; j++) bias[j] = __ldg(bsrc + ncol0 + tx * 8 + j);

        #pragma unroll
        for (int i = 0; i < 8; i++) {
            const int row  = m0 + ty * 8 + i;
            const int bidx = row >> 9;
            const int s    = row & 511;
            float* outp = g_WX + (((size_t)dir * BATCH + bidx) * SEQ + s) * G4H
                          + ncol0 + tx * 8;
            #pragma unroll
            for (int j = 0; j < 8; j++) outp[j] = acc[i][j] + bias[j];
        }
    }
}

// ---------------------------------------------------------------------------
// K2: BiLSTM recurrence. 128 CTAs = 2 dirs x 64 groups of 2 batch, 512 thr.
// Thread j owns gate row j: Whh[j][0:64] in regs, [64:128] in smem (stride 68).
// ---------------------------------------------------------------------------
__global__ void __launch_bounds__(512, 1) lstm_rec_kernel(
    const float* __restrict__ Whh_f, const float* __restrict__ Whh_b)
{
    extern __shared__ float sm2[];
    float* Wsm = sm2;                // 512*68
    float* G   = sm2 + 512 * 68;     // 2*512
    float* hsm = G + 1024;           // 2*128

    const int j   = threadIdx.x;
    const int dir = blockIdx.x >> 6;
    const int b0  = (blockIdx.x & 63) * 2;
    const float* Whh = dir ? Whh_b : Whh_f;
    const float4* wrow = (const float4*)(Whh + (size_t)j * HID);

    float wr[64];
    #pragma unroll
    for (int i = 0; i < 16; i++) {
        float4 v = wrow[i];
        wr[4*i] = v.x; wr[4*i+1] = v.y; wr[4*i+2] = v.z; wr[4*i+3] = v.w;
    }
    #pragma unroll
    for (int i = 0; i < 16; i++)
        *(float4*)&Wsm[j * 68 + i * 4] = wrow[16 + i];
    if (j < 256) hsm[j] = 0.f;
    float c = 0.f;
    __syncthreads();

    const size_t base0 = ((size_t)dir * BATCH + b0) * SEQ * (size_t)G4H;
    const size_t bstride = (size_t)SEQ * G4H;
    float wx0, wx1;
    {
        const int s0 = dir ? (SEQ - 1) : 0;
        wx0 = g_WX[base0 + (size_t)s0 * G4H + j];
        wx1 = g_WX[base0 + bstride + (size_t)s0 * G4H + j];
    }

    for (int t = 0; t < SEQ; t++) {
        const int s = dir ? (SEQ - 1 - t) : t;
        float acc0 = wx0, acc1 = wx1;
        if (t < SEQ - 1) {
            const int sn = dir ? (SEQ - 2 - t) : (t + 1);
            wx0 = g_WX[base0 + (size_t)sn * G4H + j];
            wx1 = g_WX[base0 + bstride + (size_t)sn * G4H + j];
        }
        #pragma unroll
        for (int kq = 0; kq < 16; kq++) {
            float4 h0 = *(const float4*)&hsm[kq * 4];
            float4 h1 = *(const float4*)&hsm[128 + kq * 4];
            acc0 += wr[4*kq]*h0.x + wr[4*kq+1]*h0.y + wr[4*kq+2]*h0.z + wr[4*kq+3]*h0.w;
            acc1 += wr[4*kq]*h1.x + wr[4*kq+1]*h1.y + wr[4*kq+2]*h1.z + wr[4*kq+3]*h1.w;
        }
        #pragma unroll
        for (int kq = 0; kq < 16; kq++) {
            float4 w  = *(const float4*)&Wsm[j * 68 + kq * 4];
            float4 h0 = *(const float4*)&hsm[64 + kq * 4];
            float4 h1 = *(const float4*)&hsm[192 + kq * 4];
            acc0 += w.x*h0.x + w.y*h0.y + w.z*h0.z + w.w*h0.w;
            acc1 += w.x*h1.x + w.y*h1.y + w.z*h1.z + w.w*h1.w;
        }
        G[j] = acc0; G[512 + j] = acc1;
        __syncthreads();
        if (j < 256) {
            const int b = j >> 7, u = j & 127;
            const float* Gb = G + b * 512;
            float gi = Gb[u], gf = Gb[128+u], gg = Gb[256+u], go = Gb[384+u];
            float si = 1.f / (1.f + __expf(-gi));
            float sf = 1.f / (1.f + __expf(-gf));
            float so = 1.f / (1.f + __expf(-go));
            float ea = __expf(-2.f * fabsf(gg));
            float tg = (1.f - ea) / (1.f + ea); tg = (gg < 0.f) ? -tg : tg;
            c = sf * c + si * tg;
            float eb = __expf(-2.f * fabsf(c));
            float tc = (1.f - eb) / (1.f + eb); tc = (c < 0.f) ? -tc : tc;
            float h = so * tc;
            hsm[b * 128 + u] = h;
            g_H[(((size_t)dir * BATCH + b0 + b) * SEQ + s) * HID + u] = h;
        }
        __syncthreads();
    }
}

// ---------------------------------------------------------------------------
// K3: emissions + CRF forward + gold score. 1 CTA per batch, 128 threads.
// ---------------------------------------------------------------------------
__global__ void __launch_bounds__(128) crf_kernel(
    const float* __restrict__ Wout, const float* __restrict__ bout,
    const float* __restrict__ trans, const int* __restrict__ y0,
    float* __restrict__ out)
{
    __shared__ float Wsm[NT * 256];
    __shared__ float bsm[NT];
    __shared__ float tsm[NT * NT];
    __shared__ float hsm[256];
    __shared__ float ysm[NT];
    __shared__ float score[2][NT];
    __shared__ float gold_s;
    __shared__ int   ysq[SEQ];

    const int tid = threadIdx.x;
    const int b   = blockIdx.x;
    for (int i = tid; i < NT * 256; i += 128) Wsm[i] = Wout[i];
    if (tid < NT) bsm[tid] = bout[tid];
    for (int i = tid; i < NT * NT; i += 128) tsm[i] = trans[i];  // FIX: was tid<144 guard with 128 threads
    if (tid < NT) score[0][tid] = (tid == SOS_T) ? 0.f : NEGV;
    for (int i = tid; i < SEQ; i += 128) ysq[i] = y0[b * SEQ + i];
    __syncthreads();

    const float* Hf = g_H + (size_t)b * SEQ * HID;
    const float* Hb = g_H + ((size_t)BATCH + b) * SEQ * HID;
    float hvf = Hf[tid], hvb = Hb[tid];
    const int wid = tid >> 5, lane = tid & 31;
    float gold = 0.f; int prev = SOS_T;
    int cur = 0;

    for (int s = 0; s < SEQ; s++) {
        hsm[tid] = hvf; hsm[128 + tid] = hvb;
        __syncthreads();
        if (s < SEQ - 1) { hvf = Hf[(s+1)*HID + tid]; hvb = Hb[(s+1)*HID + tid]; }
        #pragma unroll
        for (int tt = 0; tt < 3; tt++) {
            const int t = wid * 3 + tt;
            const float* wp = Wsm + t * 256 + lane * 8;
            const float* hp = hsm + lane * 8;
            float a = 0.f;
            #pragma unroll
            for (int q = 0; q < 8; q++) a += wp[q] * hp[q];
            #pragma unroll
            for (int o = 16; o > 0; o >>= 1) a += __shfl_xor_sync(0xffffffffu, a, o);
            if (lane == 0) ysm[t] = a + bsm[t];
        }
        __syncthreads();
        if (tid < NT) {
            float sc[NT], m = -1e30f;
            #pragma unroll
            for (int jj = 0; jj < NT; jj++) {
                float v = score[cur][jj] + tsm[tid * NT + jj];
                sc[jj] = v; m = fmaxf(m, v);
            }
            float sum = 0.f;
            #pragma unroll
            for (int jj = 0; jj < NT; jj++) sum += __expf(sc[jj] - m);
            score[cur ^ 1][tid] = m + __logf(sum) + ysm[tid];
        }
        if (tid == 64) {
            const int tag = ysq[s];
            gold += ysm[tag] + tsm[tag * NT + prev];
            prev = tag;
        }
        cur ^= 1;
        __syncthreads();
    }

    if (tid == 64) { gold += tsm[EOS_T * NT + prev]; gold_s = gold; }
    if (tid < NT) ysm[tid] = score[cur][tid] + tsm[EOS_T * NT + tid];
    __syncthreads();
    if (tid == 0) {
        float m = -1e30f;
        #pragma unroll
        for (int jj = 0; jj < NT; jj++) m = fmaxf(m, ysm[jj]);
        float sum = 0.f;
        #pragma unroll
        for (int jj = 0; jj < NT; jj++) sum += __expf(ysm[jj] - m);
        out[b] = m + __logf(sum) - gold_s;
    }
}

extern "C" void kernel_launch(void* const* d_in, const int* in_sizes, int n_in,
                              void* d_out, int out_size)
{
    const int*   x     = (const int*)  d_in[0];
    const int*   y0    = (const int*)  d_in[1];
    const float* embed = (const float*)d_in[2];
    const float* Wih_f = (const float*)d_in[3];
    const float* Whh_f = (const float*)d_in[4];
    const float* b_f   = (const float*)d_in[5];
    const float* Wih_b = (const float*)d_in[6];
    const float* Whh_b = (const float*)d_in[7];
    const float* b_b   = (const float*)d_in[8];
    const float* Wout  = (const float*)d_in[9];
    const float* bout  = (const float*)d_in[10];
    const float* trans = (const float*)d_in[11];

    const int smem1 = (304 * 128 + 16 * 132 + 128) * 4;     // ~164.6 KB
    const int smem2 = (512 * 68 + 1024 + 256) * 4;          // ~144.4 KB
    cudaFuncSetAttribute(input_gemm_kernel,
        cudaFuncAttributeMaxDynamicSharedMemorySize, smem1);
    cudaFuncSetAttribute(lstm_rec_kernel,
        cudaFuncAttributeMaxDynamicSharedMemorySize, smem2);

    input_gemm_kernel<<<512, 256, smem1>>>(x, embed, Wih_f, b_f, Wih_b, b_b);
    lstm_rec_kernel<<<128, 512, smem2>>>(Whh_f, Whh_b);
    crf_kernel<<<BATCH, 128>>>(Wout, bout, trans, y0, (float*)d_out);
}

// round 4
// speedup vs baseline: 1.3040x; 1.3040x over previous
#include <cuda_runtime.h>
#include <cstddef>

#define EMB_E   300
#define HID     128
#define NT      12
#define SOS_T   3
#define EOS_T   4
#define NEGV    (-10000.0f)
#define BATCH   128
#define SEQ     512
#define G4H     512
#define KC      20
#define NCH     15   /* 300 / 20 */

// Scratch (device globals; no runtime allocation allowed)
__device__ float g_WX[67108864];   // [dir][b][s][512] input proj + bias
__device__ float g_H [16777216];   // [dir][b][s][128] hidden states

// ---- packed fp32 helpers (Blackwell FFMA2 path; ptxas won't auto-fuse) ----
__device__ __forceinline__ unsigned long long pk_dup(float a) {
    unsigned long long r;
    asm("mov.b64 %0, {%1, %1};" : "=l"(r) : "f"(a));
    return r;
}
__device__ __forceinline__ unsigned long long pk2(float lo, float hi) {
    unsigned long long r;
    asm("mov.b64 %0, {%1, %2};" : "=l"(r) : "f"(lo), "f"(hi));
    return r;
}
__device__ __forceinline__ void ffma2(unsigned long long& d,
                                      unsigned long long a, unsigned long long b) {
    asm("fma.rn.f32x2 %0, %1, %2, %0;" : "+l"(d) : "l"(a), "l"(b));
}
__device__ __forceinline__ void unpk(unsigned long long v, float& lo, float& hi) {
    asm("mov.b64 {%0, %1}, %2;" : "=f"(lo), "=f"(hi) : "l"(v));
}

// ---------------------------------------------------------------------------
// K1: fused gather + input GEMM via FFMA2. Grid 4096 = 512 M x 8 N, 256 thr.
// K chunked 20, double-buffered smem, 2 CTAs/SM.
// ---------------------------------------------------------------------------
__global__ void __launch_bounds__(256, 2) input_gemm_kernel(
    const int* __restrict__ x, const float* __restrict__ embed,
    const float* __restrict__ Wih_f, const float* __restrict__ b_f,
    const float* __restrict__ Wih_b, const float* __restrict__ b_b)
{
    __shared__ __align__(16) float As[2][KC][128];
    __shared__ __align__(16) float Bs[2][KC][132];
    __shared__ int xs[128];

    const int tid = threadIdx.x;
    const int mt  = blockIdx.x >> 3;
    const int nt  = blockIdx.x & 7;
    const int m0  = mt * 128;
    const int dir   = nt >> 2;
    const int ncol0 = (nt & 3) * 128;
    const float* Wsrc = dir ? Wih_b : Wih_f;
    const float* bsrc = dir ? b_b   : b_f;

    if (tid < 128) xs[tid] = x[m0 + tid];
    __syncthreads();

    const int lm = tid & 127;
    const int kg = tid >> 7;            // 0/1: k sub-offset kg*10 within chunk
    const float* arow = embed + (size_t)xs[lm] * EMB_E + kg * 10;
    const float* brow = Wsrc + (size_t)(ncol0 + lm) * EMB_E + kg * 10;

    float2 ra[5], rb[5];
    #pragma unroll
    for (int q = 0; q < 5; q++) {
        ra[q] = *(const float2*)(arow + 2 * q);
        rb[q] = *(const float2*)(brow + 2 * q);
    }
    #pragma unroll
    for (int q = 0; q < 5; q++) {
        As[0][kg * 10 + 2 * q][lm]     = ra[q].x;
        As[0][kg * 10 + 2 * q + 1][lm] = ra[q].y;
        Bs[0][kg * 10 + 2 * q][lm]     = rb[q].x;
        Bs[0][kg * 10 + 2 * q + 1][lm] = rb[q].y;
    }
    __syncthreads();

    const int tx = tid & 15;
    const int ty = tid >> 4;

    unsigned long long acc2[8][4];
    #pragma unroll
    for (int i = 0; i < 8; i++)
        #pragma unroll
        for (int jp = 0; jp < 4; jp++) acc2[i][jp] = 0ULL;

    for (int c = 0; c < NCH; c++) {
        const int cur = c & 1;
        if (c < NCH - 1) {
            const float* a2 = arow + (c + 1) * KC;
            const float* b2 = brow + (c + 1) * KC;
            #pragma unroll
            for (int q = 0; q < 5; q++) {
                ra[q] = *(const float2*)(a2 + 2 * q);
                rb[q] = *(const float2*)(b2 + 2 * q);
            }
        }

        #pragma unroll
        for (int kk = 0; kk < KC; kk++) {
            float a[8];
            *(float4*)(a)     = *(const float4*)&As[cur][kk][ty * 8];
            *(float4*)(a + 4) = *(const float4*)&As[cur][kk][ty * 8 + 4];
            ulonglong2 t0 = *(const ulonglong2*)&Bs[cur][kk][tx * 8];
            ulonglong2 t1 = *(const ulonglong2*)&Bs[cur][kk][tx * 8 + 4];
            unsigned long long b2r[4] = {t0.x, t0.y, t1.x, t1.y};
            #pragma unroll
            for (int i = 0; i < 8; i++) {
                const unsigned long long ad = pk_dup(a[i]);
                #pragma unroll
                for (int jp = 0; jp < 4; jp++) ffma2(acc2[i][jp], ad, b2r[jp]);
            }
        }

        if (c < NCH - 1) {
            const int nxt = 1 - cur;
            #pragma unroll
            for (int q = 0; q < 5; q++) {
                As[nxt][kg * 10 + 2 * q][lm]     = ra[q].x;
                As[nxt][kg * 10 + 2 * q + 1][lm] = ra[q].y;
                Bs[nxt][kg * 10 + 2 * q][lm]     = rb[q].x;
                Bs[nxt][kg * 10 + 2 * q + 1][lm] = rb[q].y;
            }
            __syncthreads();
        }
    }

    float bias[8];
    #pragma unroll
    for (int j = 0; j < 8; j++) bias[j] = __ldg(bsrc + ncol0 + tx * 8 + j);

    #pragma unroll
    for (int i = 0; i < 8; i++) {
        const int row  = m0 + ty * 8 + i;
        const int bidx = row >> 9;
        const int s    = row & 511;
        float o[8];
        #pragma unroll
        for (int jp = 0; jp < 4; jp++) unpk(acc2[i][jp], o[2 * jp], o[2 * jp + 1]);
        #pragma unroll
        for (int j = 0; j < 8; j++) o[j] += bias[j];
        float* outp = g_WX + (((size_t)dir * BATCH + bidx) * SEQ + s) * G4H
                      + ncol0 + tx * 8;
        *(float4*)(outp)     = *(float4*)(o);
        *(float4*)(outp + 4) = *(float4*)(o + 4);
    }
}

// ---------------------------------------------------------------------------
// K2: BiLSTM recurrence with FFMA2 over batch pairs. 128 CTAs, 512 thr.
// Thread j owns gate row j: Whh[j][0:64] in regs, [64:128] in smem.
// h kept in smem as interleaved (b0,b1) pairs -> LDS yields packed operands.
// ---------------------------------------------------------------------------
__global__ void __launch_bounds__(512, 1) lstm_rec_kernel(
    const float* __restrict__ Whh_f, const float* __restrict__ Whh_b)
{
    extern __shared__ __align__(16) float sm2[];
    float* Wsm  = sm2;                 // 512*68
    float* G    = sm2 + 512 * 68;      // 2*512
    float* hsm2 = G + 1024;            // 512: pairs hsm2[2u + b]

    const int j   = threadIdx.x;
    const int dir = blockIdx.x >> 6;
    const int b0  = (blockIdx.x & 63) * 2;
    const float* Whh = dir ? Whh_b : Whh_f;
    const float4* wrow = (const float4*)(Whh + (size_t)j * HID);

    float wr[64];
    #pragma unroll
    for (int i = 0; i < 16; i++) {
        float4 v = wrow[i];
        wr[4*i] = v.x; wr[4*i+1] = v.y; wr[4*i+2] = v.z; wr[4*i+3] = v.w;
    }
    #pragma unroll
    for (int i = 0; i < 16; i++)
        *(float4*)&Wsm[j * 68 + i * 4] = wrow[16 + i];
    if (j < 512) hsm2[j] = 0.f;
    float c = 0.f;
    __syncthreads();

    const size_t base0 = ((size_t)dir * BATCH + b0) * SEQ * (size_t)G4H;
    const size_t bstride = (size_t)SEQ * G4H;
    float wx0, wx1;
    {
        const int s0 = dir ? (SEQ - 1) : 0;
        wx0 = g_WX[base0 + (size_t)s0 * G4H + j];
        wx1 = g_WX[base0 + bstride + (size_t)s0 * G4H + j];
    }

    for (int t = 0; t < SEQ; t++) {
        const int s = dir ? (SEQ - 1 - t) : t;
        unsigned long long acc = pk2(wx0, wx1);
        if (t < SEQ - 1) {
            const int sn = dir ? (SEQ - 2 - t) : (t + 1);
            wx0 = g_WX[base0 + (size_t)sn * G4H + j];
            wx1 = g_WX[base0 + bstride + (size_t)sn * G4H + j];
        }
        // k = 0..63: weights in registers
        #pragma unroll
        for (int kq = 0; kq < 16; kq++) {
            ulonglong2 hp0 = *(const ulonglong2*)&hsm2[kq * 8];
            ulonglong2 hp1 = *(const ulonglong2*)&hsm2[kq * 8 + 4];
            ffma2(acc, pk_dup(wr[4*kq+0]), hp0.x);
            ffma2(acc, pk_dup(wr[4*kq+1]), hp0.y);
            ffma2(acc, pk_dup(wr[4*kq+2]), hp1.x);
            ffma2(acc, pk_dup(wr[4*kq+3]), hp1.y);
        }
        // k = 64..127: weights in smem
        #pragma unroll
        for (int kq = 0; kq < 16; kq++) {
            float4 w = *(const float4*)&Wsm[j * 68 + kq * 4];
            ulonglong2 hp0 = *(const ulonglong2*)&hsm2[128 + kq * 8];
            ulonglong2 hp1 = *(const ulonglong2*)&hsm2[128 + kq * 8 + 4];
            ffma2(acc, pk_dup(w.x), hp0.x);
            ffma2(acc, pk_dup(w.y), hp0.y);
            ffma2(acc, pk_dup(w.z), hp1.x);
            ffma2(acc, pk_dup(w.w), hp1.y);
        }
        float a0, a1; unpk(acc, a0, a1);
        G[j] = a0; G[512 + j] = a1;
        __syncthreads();
        if (j < 256) {
            const int b = j >> 7, u = j & 127;
            const float* Gb = G + b * 512;
            float gi = Gb[u], gf = Gb[128+u], gg = Gb[256+u], go = Gb[384+u];
            float si = 1.f / (1.f + __expf(-gi));
            float sf = 1.f / (1.f + __expf(-gf));
            float so = 1.f / (1.f + __expf(-go));
            float ea = __expf(-2.f * fabsf(gg));
            float tg = (1.f - ea) / (1.f + ea); tg = (gg < 0.f) ? -tg : tg;
            c = sf * c + si * tg;
            float eb = __expf(-2.f * fabsf(c));
            float tc = (1.f - eb) / (1.f + eb); tc = (c < 0.f) ? -tc : tc;
            float h = so * tc;
            hsm2[2 * u + b] = h;
            g_H[(((size_t)dir * BATCH + b0 + b) * SEQ + s) * HID + u] = h;
        }
        __syncthreads();
    }
}

// ---------------------------------------------------------------------------
// K3: emissions + CRF forward + gold score. 1 CTA per batch, 128 threads.
// ---------------------------------------------------------------------------
__global__ void __launch_bounds__(128) crf_kernel(
    const float* __restrict__ Wout, const float* __restrict__ bout,
    const float* __restrict__ trans, const int* __restrict__ y0,
    float* __restrict__ out)
{
    __shared__ float Wsm[NT * 256];
    __shared__ float bsm[NT];
    __shared__ float tsm[NT * NT];
    __shared__ float hsm[256];
    __shared__ float ysm[NT];
    __shared__ float score[2][NT];
    __shared__ float gold_s;
    __shared__ int   ysq[SEQ];

    const int tid = threadIdx.x;
    const int b   = blockIdx.x;
    for (int i = tid; i < NT * 256; i += 128) Wsm[i] = Wout[i];
    if (tid < NT) bsm[tid] = bout[tid];
    for (int i = tid; i < NT * NT; i += 128) tsm[i] = trans[i];
    if (tid < NT) score[0][tid] = (tid == SOS_T) ? 0.f : NEGV;
    for (int i = tid; i < SEQ; i += 128) ysq[i] = y0[b * SEQ + i];
    __syncthreads();

    const float* Hf = g_H + (size_t)b * SEQ * HID;
    const float* Hb = g_H + ((size_t)BATCH + b) * SEQ * HID;
    float hvf = Hf[tid], hvb = Hb[tid];
    const int wid = tid >> 5, lane = tid & 31;
    float gold = 0.f; int prev = SOS_T;
    int cur = 0;

    for (int s = 0; s < SEQ; s++) {
        hsm[tid] = hvf; hsm[128 + tid] = hvb;
        __syncthreads();
        if (s < SEQ - 1) { hvf = Hf[(s+1)*HID + tid]; hvb = Hb[(s+1)*HID + tid]; }
        #pragma unroll
        for (int tt = 0; tt < 3; tt++) {
            const int t = wid * 3 + tt;
            const float* wp = Wsm + t * 256 + lane * 8;
            const float* hp = hsm + lane * 8;
            float a = 0.f;
            #pragma unroll
            for (int q = 0; q < 8; q++) a += wp[q] * hp[q];
            #pragma unroll
            for (int o = 16; o > 0; o >>= 1) a += __shfl_xor_sync(0xffffffffu, a, o);
            if (lane == 0) ysm[t] = a + bsm[t];
        }
        __syncthreads();
        if (tid < NT) {
            float sc[NT], m = -1e30f;
            #pragma unroll
            for (int jj = 0; jj < NT; jj++) {
                float v = score[cur][jj] + tsm[tid * NT + jj];
                sc[jj] = v; m = fmaxf(m, v);
            }
            float sum = 0.f;
            #pragma unroll
            for (int jj = 0; jj < NT; jj++) sum += __expf(sc[jj] - m);
            score[cur ^ 1][tid] = m + __logf(sum) + ysm[tid];
        }
        if (tid == 64) {
            const int tag = ysq[s];
            gold += ysm[tag] + tsm[tag * NT + prev];
            prev = tag;
        }
        cur ^= 1;
        __syncthreads();
    }

    if (tid == 64) { gold += tsm[EOS_T * NT + prev]; gold_s = gold; }
    if (tid < NT) ysm[tid] = score[cur][tid] + tsm[EOS_T * NT + tid];
    __syncthreads();
    if (tid == 0) {
        float m = -1e30f;
        #pragma unroll
        for (int jj = 0; jj < NT; jj++) m = fmaxf(m, ysm[jj]);
        float sum = 0.f;
        #pragma unroll
        for (int jj = 0; jj < NT; jj++) sum += __expf(ysm[jj] - m);
        out[b] = m + __logf(sum) - gold_s;
    }
}

extern "C" void kernel_launch(void* const* d_in, const int* in_sizes, int n_in,
                              void* d_out, int out_size)
{
    const int*   x     = (const int*)  d_in[0];
    const int*   y0    = (const int*)  d_in[1];
    const float* embed = (const float*)d_in[2];
    const float* Wih_f = (const float*)d_in[3];
    const float* Whh_f = (const float*)d_in[4];
    const float* b_f   = (const float*)d_in[5];
    const float* Wih_b = (const float*)d_in[6];
    const float* Whh_b = (const float*)d_in[7];
    const float* b_b   = (const float*)d_in[8];
    const float* Wout  = (const float*)d_in[9];
    const float* bout  = (const float*)d_in[10];
    const float* trans = (const float*)d_in[11];

    const int smem2 = (512 * 68 + 1024 + 512) * 4;   // ~144 KB
    cudaFuncSetAttribute(lstm_rec_kernel,
        cudaFuncAttributeMaxDynamicSharedMemorySize, smem2);

    input_gemm_kernel<<<4096, 256>>>(x, embed, Wih_f, b_f, Wih_b, b_b);
    lstm_rec_kernel<<<128, 512, smem2>>>(Whh_f, Whh_b);
    crf_kernel<<<BATCH, 128>>>(Wout, bout, trans, y0, (float*)d_out);
}

// round 6
// speedup vs baseline: 1.6473x; 1.2633x over previous
#include <cuda_runtime.h>
#include <cuda_bf16.h>
#include <cstddef>
#include <cstdint>

#define EMB_E   300
#define HID     128
#define NT      12
#define SOS_T   3
#define EOS_T   4
#define NEGV    (-10000.0f)
#define BATCH   128
#define SEQ     512
#define G4H     512

#define KPRIME  960           /* 3*304 + 48 pad */
#define KCH     32
#define NCHK    30            /* 960/32 */
#define MROWS   65536         /* BATCH*SEQ */

// Scratch (device globals; no runtime allocation allowed)
__device__ float g_WX[67108864];            // [dir][b][s][512]
__device__ float g_H [16777216];            // [dir][b][s][128]
__device__ __nv_bfloat16 g_Abf[62914560];   // [65536][960] split-bf16 A'
__device__ __nv_bfloat16 g_Bbf[983040];     // [1024][960]  split-bf16 B'

// ---- packed fp32 helpers (valid on plain sm_100) ----
__device__ __forceinline__ void ffma2(unsigned long long& d,
                                      unsigned long long a, unsigned long long b) {
    asm("fma.rn.f32x2 %0, %1, %2, %0;" : "+l"(d) : "l"(a), "l"(b));
}
__device__ __forceinline__ unsigned long long pk2(float lo, float hi) {
    unsigned long long r;
    asm("mov.b64 %0, {%1, %2};" : "=l"(r) : "f"(lo), "f"(hi));
    return r;
}
__device__ __forceinline__ void unpk(unsigned long long v, float& lo, float& hi) {
    asm("mov.b64 {%0, %1}, %2;" : "=f"(lo), "=f"(hi) : "l"(v));
}
__device__ __forceinline__ uint32_t smem_u32(const void* p) {
    uint32_t a;
    asm("{ .reg .u64 t; cvta.to.shared.u64 t, %1; cvt.u32.u64 %0, t; }"
        : "=r"(a) : "l"(p));
    return a;
}

// ---------------------------------------------------------------------------
// P1: build A' = [Ah | Ah | Al] per token row (gather from embed). warp/row.
// ---------------------------------------------------------------------------
__global__ void __launch_bounds__(256) prep_A_kernel(
    const int* __restrict__ x, const float* __restrict__ embed)
{
    const int w    = (blockIdx.x * 256 + threadIdx.x) >> 5;
    const int lane = threadIdx.x & 31;
    if (w >= MROWS) return;
    const float* src = embed + (size_t)x[w] * EMB_E;
    __nv_bfloat16* dst = g_Abf + (size_t)w * KPRIME;
    for (int k = lane; k < 304; k += 32) {
        float v = (k < 300) ? src[k] : 0.f;
        __nv_bfloat16 hi = __float2bfloat16(v);
        float lo = v - __bfloat162float(hi);
        dst[k]       = hi;
        dst[304 + k] = hi;
        dst[608 + k] = __float2bfloat16(lo);
    }
    if (lane < 48) dst[912 + lane] = __float2bfloat16(0.f);
}

// ---------------------------------------------------------------------------
// P2: build B' = [Bh | Bl | Bh] for both dirs (1024 rows). warp/row.
// ---------------------------------------------------------------------------
__global__ void __launch_bounds__(256) prep_B_kernel(
    const float* __restrict__ Wih_f, const float* __restrict__ Wih_b)
{
    const int w    = (blockIdx.x * 256 + threadIdx.x) >> 5;
    const int lane = threadIdx.x & 31;
    if (w >= 1024) return;
    const int dir = w >> 9, row = w & 511;
    const float* src = (dir ? Wih_b : Wih_f) + (size_t)row * EMB_E;
    __nv_bfloat16* dst = g_Bbf + (size_t)w * KPRIME;
    for (int k = lane; k < 304; k += 32) {
        float v = (k < 300) ? src[k] : 0.f;
        __nv_bfloat16 hi = __float2bfloat16(v);
        float lo = v - __bfloat162float(hi);
        dst[k]       = hi;
        dst[304 + k] = __float2bfloat16(lo);
        dst[608 + k] = hi;
    }
    if (lane < 48) dst[912 + lane] = __float2bfloat16(0.f);
}

// ---------------------------------------------------------------------------
// K1: bf16 mma.sync GEMM. Grid 4096 = 512 M x 8 N (N fast), 256 thr, 2 CTA/SM.
// 128x128 CTA tile, warp tile 64x32 (2x4 warps), K chunks of 32, dbl-buffered.
// Smem rows padded to 40 bf16 (stride-5 16B units -> conflict-free ldmatrix).
// ---------------------------------------------------------------------------
__global__ void __launch_bounds__(256, 2) mma_gemm_kernel(
    const float* __restrict__ b_f, const float* __restrict__ b_b)
{
    __shared__ __nv_bfloat16 As[2][128][40];
    __shared__ __nv_bfloat16 Bs[2][128][40];

    const int tid  = threadIdx.x;
    const int wid  = tid >> 5;
    const int lane = tid & 31;

    const int mt    = blockIdx.x >> 3;
    const int nt    = blockIdx.x & 7;
    const int m0    = mt * 128;
    const int dir   = nt >> 2;
    const int ncol0 = (nt & 3) * 128;
    const float* bsrc = dir ? b_b : b_f;

    const __nv_bfloat16* gA = g_Abf + (size_t)m0 * KPRIME;
    const __nv_bfloat16* gB = g_Bbf + ((size_t)dir * 512 + ncol0) * KPRIME;

    // global-load mapping: 512 16B units per tile, 2 per thread
    const int r0 = tid >> 2,            kq0 = tid & 3;          // unit tid
    const int r1 = (tid + 256) >> 2,    kq1 = (tid + 256) & 3;  // unit tid+256

    float4 pa0, pa1, pb0, pb1;
    {   // chunk 0 -> regs -> smem[0]
        pa0 = *(const float4*)(gA + (size_t)r0 * KPRIME + kq0 * 8);
        pa1 = *(const float4*)(gA + (size_t)r1 * KPRIME + kq1 * 8);
        pb0 = *(const float4*)(gB + (size_t)r0 * KPRIME + kq0 * 8);
        pb1 = *(const float4*)(gB + (size_t)r1 * KPRIME + kq1 * 8);
        *(float4*)&As[0][r0][kq0 * 8] = pa0;
        *(float4*)&As[0][r1][kq1 * 8] = pa1;
        *(float4*)&Bs[0][r0][kq0 * 8] = pb0;
        *(float4*)&Bs[0][r1][kq1 * 8] = pb1;
    }
    __syncthreads();

    const int warp_m = wid >> 2;        // 0..1  (64 rows)
    const int warp_n = wid & 3;         // 0..3  (32 cols)

    float acc[4][4][4];
    #pragma unroll
    for (int i = 0; i < 4; i++)
        #pragma unroll
        for (int j = 0; j < 4; j++)
            #pragma unroll
            for (int q = 0; q < 4; q++) acc[i][j][q] = 0.f;

    for (int c = 0; c < NCHK; c++) {
        const int buf = c & 1;
        if (c + 1 < NCHK) {
            const int koff = (c + 1) * KCH;
            pa0 = *(const float4*)(gA + (size_t)r0 * KPRIME + koff + kq0 * 8);
            pa1 = *(const float4*)(gA + (size_t)r1 * KPRIME + koff + kq1 * 8);
            pb0 = *(const float4*)(gB + (size_t)r0 * KPRIME + koff + kq0 * 8);
            pb1 = *(const float4*)(gB + (size_t)r1 * KPRIME + koff + kq1 * 8);
        }

        #pragma unroll
        for (int ks = 0; ks < 2; ks++) {
            uint32_t a[4][4];
            #pragma unroll
            for (int mf = 0; mf < 4; mf++) {
                uint32_t addr = smem_u32(
                    &As[buf][warp_m * 64 + mf * 16 + (lane & 15)]
                           [ks * 16 + (lane >> 4) * 8]);
                asm volatile(
                    "ldmatrix.sync.aligned.m8n8.x4.shared.b16 {%0,%1,%2,%3}, [%4];"
                    : "=r"(a[mf][0]), "=r"(a[mf][1]), "=r"(a[mf][2]), "=r"(a[mf][3])
                    : "r"(addr));
            }
            #pragma unroll
            for (int nf = 0; nf < 4; nf++) {
                uint32_t b0, b1;
                uint32_t addr = smem_u32(
                    &Bs[buf][warp_n * 32 + nf * 8 + (lane & 7)]
                           [ks * 16 + ((lane >> 3) & 1) * 8]);
                asm volatile(
                    "ldmatrix.sync.aligned.m8n8.x2.shared.b16 {%0,%1}, [%2];"
                    : "=r"(b0), "=r"(b1) : "r"(addr));
                #pragma unroll
                for (int mf = 0; mf < 4; mf++) {
                    asm volatile(
                        "mma.sync.aligned.m16n8k16.row.col.f32.bf16.bf16.f32 "
                        "{%0,%1,%2,%3}, {%4,%5,%6,%7}, {%8,%9}, {%0,%1,%2,%3};"
                        : "+f"(acc[mf][nf][0]), "+f"(acc[mf][nf][1]),
                          "+f"(acc[mf][nf][2]), "+f"(acc[mf][nf][3])
                        : "r"(a[mf][0]), "r"(a[mf][1]), "r"(a[mf][2]), "r"(a[mf][3]),
                          "r"(b0), "r"(b1));
                }
            }
        }

        __syncthreads();
        if (c + 1 < NCHK) {
            const int nxt = buf ^ 1;
            *(float4*)&As[nxt][r0][kq0 * 8] = pa0;
            *(float4*)&As[nxt][r1][kq1 * 8] = pa1;
            *(float4*)&Bs[nxt][r0][kq0 * 8] = pb0;
            *(float4*)&Bs[nxt][r1][kq1 * 8] = pb1;
            __syncthreads();
        }
    }

    // epilogue: bias + store
    #pragma unroll
    for (int nf = 0; nf < 4; nf++) {
        const int col = ncol0 + warp_n * 32 + nf * 8 + (lane & 3) * 2;
        const float bx = __ldg(bsrc + col);
        const float by = __ldg(bsrc + col + 1);
        #pragma unroll
        for (int mf = 0; mf < 4; mf++) {
            const int ra = m0 + warp_m * 64 + mf * 16 + (lane >> 2);
            #pragma unroll
            for (int h = 0; h < 2; h++) {
                const int row  = ra + h * 8;
                const int bidx = row >> 9;
                const int s    = row & 511;
                float2 o;
                o.x = acc[mf][nf][2 * h]     + bx;
                o.y = acc[mf][nf][2 * h + 1] + by;
                *(float2*)(g_WX + (((size_t)dir * BATCH + bidx) * SEQ + s) * G4H + col) = o;
            }
        }
    }
}

// ---------------------------------------------------------------------------
// K2: BiLSTM recurrence, FFMA2 over natural k-pairs (no dup movs).
// 128 CTAs = 2 dirs x 64 pairs of batch, 512 threads = 1 thread / gate row.
// ---------------------------------------------------------------------------
__global__ void __launch_bounds__(512, 1) lstm_rec_kernel(
    const float* __restrict__ Whh_f, const float* __restrict__ Whh_b)
{
    extern __shared__ __align__(16) float sm2[];
    float* Wsm = sm2;                 // 512*68  (k 64..127 per row)
    float* G   = sm2 + 512 * 68;      // 2*512
    float* hsm = G + 1024;            // 2*128

    const int j   = threadIdx.x;
    const int dir = blockIdx.x >> 6;
    const int b0  = (blockIdx.x & 63) * 2;
    const float* Whh = dir ? Whh_b : Whh_f;
    const float4* wrow = (const float4*)(Whh + (size_t)j * HID);

    unsigned long long wp[32];        // k<64 packed natural pairs
    #pragma unroll
    for (int i = 0; i < 16; i++) {
        float4 v = wrow[i];
        wp[2*i]   = pk2(v.x, v.y);
        wp[2*i+1] = pk2(v.z, v.w);
    }
    #pragma unroll
    for (int i = 0; i < 16; i++)
        *(float4*)&Wsm[j * 68 + i * 4] = wrow[16 + i];
    if (j < 256) hsm[j] = 0.f;
    float c = 0.f;
    __syncthreads();

    const size_t base0 = ((size_t)dir * BATCH + b0) * SEQ * (size_t)G4H;
    const size_t bstride = (size_t)SEQ * G4H;
    float wx0, wx1;
    {
        const int s0 = dir ? (SEQ - 1) : 0;
        wx0 = g_WX[base0 + (size_t)s0 * G4H + j];
        wx1 = g_WX[base0 + bstride + (size_t)s0 * G4H + j];
    }

    for (int t = 0; t < SEQ; t++) {
        const int s = dir ? (SEQ - 1 - t) : t;
        unsigned long long acc0 = 0ULL, acc1 = 0ULL;
        const float cwx0 = wx0, cwx1 = wx1;
        if (t < SEQ - 1) {
            const int sn = dir ? (SEQ - 2 - t) : (t + 1);
            wx0 = g_WX[base0 + (size_t)sn * G4H + j];
            wx1 = g_WX[base0 + bstride + (size_t)sn * G4H + j];
        }
        #pragma unroll
        for (int kq = 0; kq < 16; kq++) {
            ulonglong2 h0 = *(const ulonglong2*)&hsm[kq * 4];
            ulonglong2 h1 = *(const ulonglong2*)&hsm[128 + kq * 4];
            ffma2(acc0, wp[2*kq],   h0.x);
            ffma2(acc0, wp[2*kq+1], h0.y);
            ffma2(acc1, wp[2*kq],   h1.x);
            ffma2(acc1, wp[2*kq+1], h1.y);
        }
        #pragma unroll
        for (int kq = 0; kq < 16; kq++) {
            ulonglong2 w  = *(const ulonglong2*)&Wsm[j * 68 + kq * 4];
            ulonglong2 h0 = *(const ulonglong2*)&hsm[64 + kq * 4];
            ulonglong2 h1 = *(const ulonglong2*)&hsm[192 + kq * 4];
            ffma2(acc0, w.x, h0.x);
            ffma2(acc0, w.y, h0.y);
            ffma2(acc1, w.x, h1.x);
            ffma2(acc1, w.y, h1.y);
        }
        float a0l, a0h, a1l, a1h;
        unpk(acc0, a0l, a0h); unpk(acc1, a1l, a1h);
        G[j] = a0l + a0h + cwx0; G[512 + j] = a1l + a1h + cwx1;
        __syncthreads();
        if (j < 256) {
            const int b = j >> 7, u = j & 127;
            const float* Gb = G + b * 512;
            float gi = Gb[u], gf = Gb[128+u], gg = Gb[256+u], go = Gb[384+u];
            float si = 1.f / (1.f + __expf(-gi));
            float sf = 1.f / (1.f + __expf(-gf));
            float so = 1.f / (1.f + __expf(-go));
            float ea = __expf(-2.f * fabsf(gg));
            float tg = (1.f - ea) / (1.f + ea); tg = (gg < 0.f) ? -tg : tg;
            c = sf * c + si * tg;
            float eb = __expf(-2.f * fabsf(c));
            float tc = (1.f - eb) / (1.f + eb); tc = (c < 0.f) ? -tc : tc;
            float h = so * tc;
            hsm[b * 128 + u] = h;
            g_H[(((size_t)dir * BATCH + b0 + b) * SEQ + s) * HID + u] = h;
        }
        __syncthreads();
    }
}

// ---------------------------------------------------------------------------
// K3: emissions + CRF forward + gold score. 1 CTA per batch, 128 threads.
// ---------------------------------------------------------------------------
__global__ void __launch_bounds__(128) crf_kernel(
    const float* __restrict__ Wout, const float* __restrict__ bout,
    const float* __restrict__ trans, const int* __restrict__ y0,
    float* __restrict__ out)
{
    __shared__ float Wsm[NT * 256];
    __shared__ float bsm[NT];
    __shared__ float tsm[NT * NT];
    __shared__ float hsm[256];
    __shared__ float ysm[NT];
    __shared__ float score[2][NT];
    __shared__ float gold_s;
    __shared__ int   ysq[SEQ];

    const int tid = threadIdx.x;
    const int b   = blockIdx.x;
    for (int i = tid; i < NT * 256; i += 128) Wsm[i] = Wout[i];
    if (tid < NT) bsm[tid] = bout[tid];
    for (int i = tid; i < NT * NT; i += 128) tsm[i] = trans[i];
    if (tid < NT) score[0][tid] = (tid == SOS_T) ? 0.f : NEGV;
    for (int i = tid; i < SEQ; i += 128) ysq[i] = y0[b * SEQ + i];
    __syncthreads();

    const float* Hf = g_H + (size_t)b * SEQ * HID;
    const float* Hb = g_H + ((size_t)BATCH + b) * SEQ * HID;
    float hvf = Hf[tid], hvb = Hb[tid];
    const int wid = tid >> 5, lane = tid & 31;
    float gold = 0.f; int prev = SOS_T;
    int cur = 0;

    for (int s = 0; s < SEQ; s++) {
        hsm[tid] = hvf; hsm[128 + tid] = hvb;
        __syncthreads();
        if (s < SEQ - 1) { hvf = Hf[(s+1)*HID + tid]; hvb = Hb[(s+1)*HID + tid]; }
        #pragma unroll
        for (int tt = 0; tt < 3; tt++) {
            const int t = wid * 3 + tt;
            const float* wp = Wsm + t * 256 + lane * 8;
            const float* hp = hsm + lane * 8;
            float a = 0.f;
            #pragma unroll
            for (int q = 0; q < 8; q++) a += wp[q] * hp[q];
            #pragma unroll
            for (int o = 16; o > 0; o >>= 1) a += __shfl_xor_sync(0xffffffffu, a, o);
            if (lane == 0) ysm[t] = a + bsm[t];
        }
        __syncthreads();
        if (tid < NT) {
            float sc[NT], m = -1e30f;
            #pragma unroll
            for (int jj = 0; jj < NT; jj++) {
                float v = score[cur][jj] + tsm[tid * NT + jj];
                sc[jj] = v; m = fmaxf(m, v);
            }
            float sum = 0.f;
            #pragma unroll
            for (int jj = 0; jj < NT; jj++) sum += __expf(sc[jj] - m);
            score[cur ^ 1][tid] = m + __logf(sum) + ysm[tid];
        }
        if (tid == 64) {
            const int tag = ysq[s];
            gold += ysm[tag] + tsm[tag * NT + prev];
            prev = tag;
        }
        cur ^= 1;
        __syncthreads();
    }

    if (tid == 64) { gold += tsm[EOS_T * NT + prev]; gold_s = gold; }
    if (tid < NT) ysm[tid] = score[cur][tid] + tsm[EOS_T * NT + tid];
    __syncthreads();
    if (tid == 0) {
        float m = -1e30f;
        #pragma unroll
        for (int jj = 0; jj < NT; jj++) m = fmaxf(m, ysm[jj]);
        float sum = 0.f;
        #pragma unroll
        for (int jj = 0; jj < NT; jj++) sum += __expf(ysm[jj] - m);
        out[b] = m + __logf(sum) - gold_s;
    }
}

extern "C" void kernel_launch(void* const* d_in, const int* in_sizes, int n_in,
                              void* d_out, int out_size)
{
    const int*   x     = (const int*)  d_in[0];
    const int*   y0    = (const int*)  d_in[1];
    const float* embed = (const float*)d_in[2];
    const float* Wih_f = (const float*)d_in[3];
    const float* Whh_f = (const float*)d_in[4];
    const float* b_f   = (const float*)d_in[5];
    const float* Wih_b = (const float*)d_in[6];
    const float* Whh_b = (const float*)d_in[7];
    const float* b_b   = (const float*)d_in[8];
    const float* Wout  = (const float*)d_in[9];
    const float* bout  = (const float*)d_in[10];
    const float* trans = (const float*)d_in[11];

    const int smem2 = (512 * 68 + 1024 + 256) * 4;
    cudaFuncSetAttribute(lstm_rec_kernel,
        cudaFuncAttributeMaxDynamicSharedMemorySize, smem2);

    prep_A_kernel<<<MROWS / 8, 256>>>(x, embed);
    prep_B_kernel<<<128, 256>>>(Wih_f, Wih_b);
    mma_gemm_kernel<<<4096, 256>>>(b_f, b_b);
    lstm_rec_kernel<<<128, 512, smem2>>>(Whh_f, Whh_b);
    crf_kernel<<<BATCH, 128>>>(Wout, bout, trans, y0, (float*)d_out);
}

// round 8
// speedup vs baseline: 1.7114x; 1.0389x over previous
#include <cuda_runtime.h>
#include <cuda_bf16.h>
#include <cstddef>
#include <cstdint>

#define EMB_E   300
#define HID     128
#define NT      12
#define SOS_T   3
#define EOS_T   4
#define NEGV    (-10000.0f)
#define BATCH   128
#define SEQ     512
#define G4H     512

#define KPRIME  960           /* 3*304 + 48 pad */
#define KCH     32
#define NCHK    30            /* 960/32 */
#define MROWS   65536         /* BATCH*SEQ */

// Scratch (device globals; no runtime allocation allowed)
// g_WX layout: [dir][b][s][u][gate]  (gate-interleaved, float4 per unit)
__device__ float g_WX[67108864];
__device__ float g_H [16777216];            // [dir][b][s][128]
__device__ __nv_bfloat16 g_Abf[62914560];   // [65536][960] split-bf16 A'
__device__ __nv_bfloat16 g_Bbf[983040];     // [1024][960]  split-bf16 B'

// ---- packed fp32 helpers (valid on plain sm_100) ----
__device__ __forceinline__ void ffma2(unsigned long long& d,
                                      unsigned long long a, unsigned long long b) {
    asm("fma.rn.f32x2 %0, %1, %2, %0;" : "+l"(d) : "l"(a), "l"(b));
}
__device__ __forceinline__ unsigned long long pk2(float lo, float hi) {
    unsigned long long r;
    asm("mov.b64 %0, {%1, %2};" : "=l"(r) : "f"(lo), "f"(hi));
    return r;
}
__device__ __forceinline__ void unpk(unsigned long long v, float& lo, float& hi) {
    asm("mov.b64 {%0, %1}, %2;" : "=f"(lo), "=f"(hi) : "l"(v));
}
__device__ __forceinline__ uint32_t smem_u32(const void* p) {
    uint32_t a;
    asm("{ .reg .u64 t; cvta.to.shared.u64 t, %1; cvt.u32.u64 %0, t; }"
        : "=r"(a) : "l"(p));
    return a;
}

// ---------------------------------------------------------------------------
// P1: build A' = [Ah | Ah | Al] per token row (gather from embed). warp/row.
// ---------------------------------------------------------------------------
__global__ void __launch_bounds__(256) prep_A_kernel(
    const int* __restrict__ x, const float* __restrict__ embed)
{
    const int w    = (blockIdx.x * 256 + threadIdx.x) >> 5;
    const int lane = threadIdx.x & 31;
    if (w >= MROWS) return;
    const float* src = embed + (size_t)x[w] * EMB_E;
    __nv_bfloat16* dst = g_Abf + (size_t)w * KPRIME;
    for (int k = lane; k < 304; k += 32) {
        float v = (k < 300) ? src[k] : 0.f;
        __nv_bfloat16 hi = __float2bfloat16(v);
        float lo = v - __bfloat162float(hi);
        dst[k]       = hi;
        dst[304 + k] = hi;
        dst[608 + k] = __float2bfloat16(lo);
    }
    if (lane < 48) dst[912 + lane] = __float2bfloat16(0.f);
}

// ---------------------------------------------------------------------------
// P2: build B' = [Bh | Bl | Bh] for both dirs (1024 rows). warp/row.
// ---------------------------------------------------------------------------
__global__ void __launch_bounds__(256) prep_B_kernel(
    const float* __restrict__ Wih_f, const float* __restrict__ Wih_b)
{
    const int w    = (blockIdx.x * 256 + threadIdx.x) >> 5;
    const int lane = threadIdx.x & 31;
    if (w >= 1024) return;
    const int dir = w >> 9, row = w & 511;
    const float* src = (dir ? Wih_b : Wih_f) + (size_t)row * EMB_E;
    __nv_bfloat16* dst = g_Bbf + (size_t)w * KPRIME;
    for (int k = lane; k < 304; k += 32) {
        float v = (k < 300) ? src[k] : 0.f;
        __nv_bfloat16 hi = __float2bfloat16(v);
        float lo = v - __bfloat162float(hi);
        dst[k]       = hi;
        dst[304 + k] = __float2bfloat16(lo);
        dst[608 + k] = hi;
    }
    if (lane < 48) dst[912 + lane] = __float2bfloat16(0.f);
}

// ---------------------------------------------------------------------------
// K1: bf16 mma.sync GEMM. Grid 4096 = 512 M x 8 N (N fast), 256 thr, 2 CTA/SM.
// Epilogue stores gate-interleaved layout for K2's single-LDG.128 wx fetch.
// ---------------------------------------------------------------------------
__global__ void __launch_bounds__(256, 2) mma_gemm_kernel(
    const float* __restrict__ b_f, const float* __restrict__ b_b)
{
    __shared__ __nv_bfloat16 As[2][128][40];
    __shared__ __nv_bfloat16 Bs[2][128][40];

    const int tid  = threadIdx.x;
    const int wid  = tid >> 5;
    const int lane = tid & 31;

    const int mt    = blockIdx.x >> 3;
    const int nt    = blockIdx.x & 7;
    const int m0    = mt * 128;
    const int dir   = nt >> 2;
    const int ncol0 = (nt & 3) * 128;
    const float* bsrc = dir ? b_b : b_f;

    const __nv_bfloat16* gA = g_Abf + (size_t)m0 * KPRIME;
    const __nv_bfloat16* gB = g_Bbf + ((size_t)dir * 512 + ncol0) * KPRIME;

    const int r0 = tid >> 2,            kq0 = tid & 3;
    const int r1 = (tid + 256) >> 2,    kq1 = (tid + 256) & 3;

    float4 pa0, pa1, pb0, pb1;
    {
        pa0 = *(const float4*)(gA + (size_t)r0 * KPRIME + kq0 * 8);
        pa1 = *(const float4*)(gA + (size_t)r1 * KPRIME + kq1 * 8);
        pb0 = *(const float4*)(gB + (size_t)r0 * KPRIME + kq0 * 8);
        pb1 = *(const float4*)(gB + (size_t)r1 * KPRIME + kq1 * 8);
        *(float4*)&As[0][r0][kq0 * 8] = pa0;
        *(float4*)&As[0][r1][kq1 * 8] = pa1;
        *(float4*)&Bs[0][r0][kq0 * 8] = pb0;
        *(float4*)&Bs[0][r1][kq1 * 8] = pb1;
    }
    __syncthreads();

    const int warp_m = wid >> 2;
    const int warp_n = wid & 3;

    float acc[4][4][4];
    #pragma unroll
    for (int i = 0; i < 4; i++)
        #pragma unroll
        for (int j = 0; j < 4; j++)
            #pragma unroll
            for (int q = 0; q < 4; q++) acc[i][j][q] = 0.f;

    for (int c = 0; c < NCHK; c++) {
        const int buf = c & 1;
        if (c + 1 < NCHK) {
            const int koff = (c + 1) * KCH;
            pa0 = *(const float4*)(gA + (size_t)r0 * KPRIME + koff + kq0 * 8);
            pa1 = *(const float4*)(gA + (size_t)r1 * KPRIME + koff + kq1 * 8);
            pb0 = *(const float4*)(gB + (size_t)r0 * KPRIME + koff + kq0 * 8);
            pb1 = *(const float4*)(gB + (size_t)r1 * KPRIME + koff + kq1 * 8);
        }

        #pragma unroll
        for (int ks = 0; ks < 2; ks++) {
            uint32_t a[4][4];
            #pragma unroll
            for (int mf = 0; mf < 4; mf++) {
                uint32_t addr = smem_u32(
                    &As[buf][warp_m * 64 + mf * 16 + (lane & 15)]
                           [ks * 16 + (lane >> 4) * 8]);
                asm volatile(
                    "ldmatrix.sync.aligned.m8n8.x4.shared.b16 {%0,%1,%2,%3}, [%4];"
                    : "=r"(a[mf][0]), "=r"(a[mf][1]), "=r"(a[mf][2]), "=r"(a[mf][3])
                    : "r"(addr));
            }
            #pragma unroll
            for (int nf = 0; nf < 4; nf++) {
                uint32_t b0, b1;
                uint32_t addr = smem_u32(
                    &Bs[buf][warp_n * 32 + nf * 8 + (lane & 7)]
                           [ks * 16 + ((lane >> 3) & 1) * 8]);
                asm volatile(
                    "ldmatrix.sync.aligned.m8n8.x2.shared.b16 {%0,%1}, [%2];"
                    : "=r"(b0), "=r"(b1) : "r"(addr));
                #pragma unroll
                for (int mf = 0; mf < 4; mf++) {
                    asm volatile(
                        "mma.sync.aligned.m16n8k16.row.col.f32.bf16.bf16.f32 "
                        "{%0,%1,%2,%3}, {%4,%5,%6,%7}, {%8,%9}, {%0,%1,%2,%3};"
                        : "+f"(acc[mf][nf][0]), "+f"(acc[mf][nf][1]),
                          "+f"(acc[mf][nf][2]), "+f"(acc[mf][nf][3])
                        : "r"(a[mf][0]), "r"(a[mf][1]), "r"(a[mf][2]), "r"(a[mf][3]),
                          "r"(b0), "r"(b1));
                }
            }
        }

        __syncthreads();
        if (c + 1 < NCHK) {
            const int nxt = buf ^ 1;
            *(float4*)&As[nxt][r0][kq0 * 8] = pa0;
            *(float4*)&As[nxt][r1][kq1 * 8] = pa1;
            *(float4*)&Bs[nxt][r0][kq0 * 8] = pb0;
            *(float4*)&Bs[nxt][r1][kq1 * 8] = pb1;
            __syncthreads();
        }
    }

    // epilogue: bias + store, gate-interleaved: off = (c&127)*4 + (c>>7)
    #pragma unroll
    for (int nf = 0; nf < 4; nf++) {
        const int col = ncol0 + warp_n * 32 + nf * 8 + (lane & 3) * 2;
        const float bx = __ldg(bsrc + col);
        const float by = __ldg(bsrc + col + 1);
        const int off0 = ((col & 127) << 2) + (col >> 7);
        const int off1 = (((col + 1) & 127) << 2) + ((col + 1) >> 7);
        #pragma unroll
        for (int mf = 0; mf < 4; mf++) {
            const int ra = m0 + warp_m * 64 + mf * 16 + (lane >> 2);
            #pragma unroll
            for (int h = 0; h < 2; h++) {
                const int row  = ra + h * 8;
                const int bidx = row >> 9;
                const int s    = row & 511;
                float* base = g_WX + (((size_t)dir * BATCH + bidx) * SEQ + s) * G4H;
                base[off0] = acc[mf][nf][2 * h]     + bx;
                base[off1] = acc[mf][nf][2 * h + 1] + by;
            }
        }
    }
}

// ---------------------------------------------------------------------------
// K2 v3: BiLSTM recurrence. 128 CTAs = 2 dirs x 64 batch-pairs, 256 threads.
// Thread (u, khalf): all 4 gate rows of unit u, both batches, over 64-k half.
// Weights: k-chunk 32/row in regs, 32/row in per-warp transposed smem.
// One barrier/step; ping-pong hsm; shfl-combined k-halves.
// ---------------------------------------------------------------------------
__global__ void __launch_bounds__(256) lstm_rec_kernel(
    const float* __restrict__ Whh_f, const float* __restrict__ Whh_b)
{
    extern __shared__ __align__(16) float sm2[];
    float* Wsm = sm2;                 // [8 warps][32 slots][32 lanes] float4 = 128KB
    float* hsm = sm2 + 32768;         // [2 bufs][2 batch][128] = 512 floats

    const int tid  = threadIdx.x;
    const int u    = tid >> 1;
    const int half = tid & 1;
    const int w    = tid >> 5;
    const int lane = tid & 31;
    const int dir  = blockIdx.x >> 6;
    const int b0   = (blockIdx.x & 63) * 2;
    const float* Whh = dir ? Whh_b : Whh_f;
    const int kbase = half * 64;

    // reg weights: rows u+128r, k in [kbase, kbase+32) -> 16 u64 pairs per row
    unsigned long long wreg[4][16];
    #pragma unroll
    for (int r = 0; r < 4; r++) {
        const float* row = Whh + (size_t)(u + 128 * r) * HID + kbase;
        #pragma unroll
        for (int q = 0; q < 8; q++) {
            float4 v = *(const float4*)(row + 4 * q);
            wreg[r][2 * q]     = pk2(v.x, v.y);
            wreg[r][2 * q + 1] = pk2(v.z, v.w);
        }
    }
    // smem weights: rows u+128r, k in [kbase+32, kbase+64): 8 float4 per row
    {
        float4* wsm4 = (float4*)Wsm;
        #pragma unroll
        for (int r = 0; r < 4; r++) {
            const float* row = Whh + (size_t)(u + 128 * r) * HID + kbase + 32;
            #pragma unroll
            for (int j = 0; j < 8; j++)
                wsm4[((w * 32 + r * 8 + j) << 5) + lane] = *(const float4*)(row + 4 * j);
        }
    }
    for (int i = tid; i < 512; i += 256) hsm[i] = 0.f;
    float cc = 0.f;
    __syncthreads();

    const float* wxbase = g_WX + ((size_t)dir * BATCH + b0 + half) * SEQ * (size_t)G4H;
    const int s0 = dir ? (SEQ - 1) : 0;
    float4 wx = __ldg((const float4*)(wxbase + (size_t)s0 * G4H + u * 4));

    const float4* wsm4r = (const float4*)Wsm + ((size_t)w << 10) + lane;

    for (int t = 0; t < SEQ; t++) {
        const int s = dir ? (SEQ - 1 - t) : t;
        const float4 cwx = wx;
        if (t < SEQ - 1) {
            const int sn = dir ? (SEQ - 2 - t) : (t + 1);
            wx = __ldg((const float4*)(wxbase + (size_t)sn * G4H + u * 4));
        }
        const float* hb = hsm + ((t & 1) << 8);

        unsigned long long acc[4][2];
        #pragma unroll
        for (int r = 0; r < 4; r++) { acc[r][0] = 0ULL; acc[r][1] = 0ULL; }

        // reg-weight part: k in [kbase, kbase+32)
        #pragma unroll
        for (int q = 0; q < 8; q++) {
            ulonglong2 hA = *(const ulonglong2*)(hb + kbase + 4 * q);
            ulonglong2 hB = *(const ulonglong2*)(hb + 128 + kbase + 4 * q);
            #pragma unroll
            for (int r = 0; r < 4; r++) {
                ffma2(acc[r][0], wreg[r][2 * q],     hA.x);
                ffma2(acc[r][0], wreg[r][2 * q + 1], hA.y);
                ffma2(acc[r][1], wreg[r][2 * q],     hB.x);
                ffma2(acc[r][1], wreg[r][2 * q + 1], hB.y);
            }
        }
        // smem-weight part: k in [kbase+32, kbase+64)
        #pragma unroll
        for (int j = 0; j < 8; j++) {
            ulonglong2 hA = *(const ulonglong2*)(hb + kbase + 32 + 4 * j);
            ulonglong2 hB = *(const ulonglong2*)(hb + 128 + kbase + 32 + 4 * j);
            #pragma unroll
            for (int r = 0; r < 4; r++) {
                ulonglong2 wv = *(const ulonglong2*)(wsm4r + (((r << 3) + j) << 5));
                ffma2(acc[r][0], wv.x, hA.x);
                ffma2(acc[r][0], wv.y, hA.y);
                ffma2(acc[r][1], wv.x, hB.x);
                ffma2(acc[r][1], wv.y, hB.y);
            }
        }

        // combine packed halves + k-half lane pair
        float d0[4], d1[4];
        #pragma unroll
        for (int r = 0; r < 4; r++) {
            float lo, hi;
            unpk(acc[r][0], lo, hi); d0[r] = lo + hi;
            unpk(acc[r][1], lo, hi); d1[r] = lo + hi;
        }
        #pragma unroll
        for (int r = 0; r < 4; r++) {
            d0[r] += __shfl_xor_sync(0xffffffffu, d0[r], 1);
            d1[r] += __shfl_xor_sync(0xffffffffu, d1[r], 1);
        }

        const float gi = (half ? d1[0] : d0[0]) + cwx.x;
        const float gf = (half ? d1[1] : d0[1]) + cwx.y;
        const float gg = (half ? d1[2] : d0[2]) + cwx.z;
        const float go = (half ? d1[3] : d0[3]) + cwx.w;

        float si = 1.f / (1.f + __expf(-gi));
        float sf = 1.f / (1.f + __expf(-gf));
        float so = 1.f / (1.f + __expf(-go));
        float ea = __expf(-2.f * fabsf(gg));
        float tg = (1.f - ea) / (1.f + ea); tg = (gg < 0.f) ? -tg : tg;
        cc = sf * cc + si * tg;
        float eb = __expf(-2.f * fabsf(cc));
        float tc = (1.f - eb) / (1.f + eb); tc = (cc < 0.f) ? -tc : tc;
        const float h = so * tc;

        hsm[(((t + 1) & 1) << 8) + (half << 7) + u] = h;
        g_H[(((size_t)dir * BATCH + b0 + half) * SEQ + s) * HID + u] = h;
        __syncthreads();
    }
}

// ---------------------------------------------------------------------------
// K3: emissions + CRF forward + gold score. 1 CTA per batch, 128 threads.
// ---------------------------------------------------------------------------
__global__ void __launch_bounds__(128) crf_kernel(
    const float* __restrict__ Wout, const float* __restrict__ bout,
    const float* __restrict__ trans, const int* __restrict__ y0,
    float* __restrict__ out)
{
    __shared__ float Wsm[NT * 256];
    __shared__ float bsm[NT];
    __shared__ float tsm[NT * NT];
    __shared__ float hsm[256];
    __shared__ float ysm[NT];
    __shared__ float score[2][NT];
    __shared__ float gold_s;
    __shared__ int   ysq[SEQ];

    const int tid = threadIdx.x;
    const int b   = blockIdx.x;
    for (int i = tid; i < NT * 256; i += 128) Wsm[i] = Wout[i];
    if (tid < NT) bsm[tid] = bout[tid];
    for (int i = tid; i < NT * NT; i += 128) tsm[i] = trans[i];
    if (tid < NT) score[0][tid] = (tid == SOS_T) ? 0.f : NEGV;
    for (int i = tid; i < SEQ; i += 128) ysq[i] = y0[b * SEQ + i];
    __syncthreads();

    const float* Hf = g_H + (size_t)b * SEQ * HID;
    const float* Hb = g_H + ((size_t)BATCH + b) * SEQ * HID;
    float hvf = Hf[tid], hvb = Hb[tid];
    const int wid = tid >> 5, lane = tid & 31;
    float gold = 0.f; int prev = SOS_T;
    int cur = 0;

    for (int s = 0; s < SEQ; s++) {
        hsm[tid] = hvf; hsm[128 + tid] = hvb;
        __syncthreads();
        if (s < SEQ - 1) { hvf = Hf[(s+1)*HID + tid]; hvb = Hb[(s+1)*HID + tid]; }
        #pragma unroll
        for (int tt = 0; tt < 3; tt++) {
            const int t = wid * 3 + tt;
            const float* wp = Wsm + t * 256 + lane * 8;
            const float* hp = hsm + lane * 8;
            float a = 0.f;
            #pragma unroll
            for (int q = 0; q < 8; q++) a += wp[q] * hp[q];
            #pragma unroll
            for (int o = 16; o > 0; o >>= 1) a += __shfl_xor_sync(0xffffffffu, a, o);
            if (lane == 0) ysm[t] = a + bsm[t];
        }
        __syncthreads();
        if (tid < NT) {
            float sc[NT], m = -1e30f;
            #pragma unroll
            for (int jj = 0; jj < NT; jj++) {
                float v = score[cur][jj] + tsm[tid * NT + jj];
                sc[jj] = v; m = fmaxf(m, v);
            }
            float sum = 0.f;
            #pragma unroll
            for (int jj = 0; jj < NT; jj++) sum += __expf(sc[jj] - m);
            score[cur ^ 1][tid] = m + __logf(sum) + ysm[tid];
        }
        if (tid == 64) {
            const int tag = ysq[s];
            gold += ysm[tag] + tsm[tag * NT + prev];
            prev = tag;
        }
        cur ^= 1;
        __syncthreads();
    }

    if (tid == 64) { gold += tsm[EOS_T * NT + prev]; gold_s = gold; }
    if (tid < NT) ysm[tid] = score[cur][tid] + tsm[EOS_T * NT + tid];
    __syncthreads();
    if (tid == 0) {
        float m = -1e30f;
        #pragma unroll
        for (int jj = 0; jj < NT; jj++) m = fmaxf(m, ysm[jj]);
        float sum = 0.f;
        #pragma unroll
        for (int jj = 0; jj < NT; jj++) sum += __expf(ysm[jj] - m);
        out[b] = m + __logf(sum) - gold_s;
    }
}

extern "C" void kernel_launch(void* const* d_in, const int* in_sizes, int n_in,
                              void* d_out, int out_size)
{
    const int*   x     = (const int*)  d_in[0];
    const int*   y0    = (const int*)  d_in[1];
    const float* embed = (const float*)d_in[2];
    const float* Wih_f = (const float*)d_in[3];
    const float* Whh_f = (const float*)d_in[4];
    const float* b_f   = (const float*)d_in[5];
    const float* Wih_b = (const float*)d_in[6];
    const float* Whh_b = (const float*)d_in[7];
    const float* b_b   = (const float*)d_in[8];
    const float* Wout  = (const float*)d_in[9];
    const float* bout  = (const float*)d_in[10];
    const float* trans = (const float*)d_in[11];

    const int smem2 = 32768 * 4 + 512 * 4;   // 128KB weights + hsm
    cudaFuncSetAttribute(lstm_rec_kernel,
        cudaFuncAttributeMaxDynamicSharedMemorySize, smem2);

    prep_A_kernel<<<MROWS / 8, 256>>>(x, embed);
    prep_B_kernel<<<128, 256>>>(Wih_f, Wih_b);
    mma_gemm_kernel<<<4096, 256>>>(b_f, b_b);
    lstm_rec_kernel<<<128, 256, smem2>>>(Whh_f, Whh_b);
    crf_kernel<<<BATCH, 128>>>(Wout, bout, trans, y0, (float*)d_out);
}

// round 9
// speedup vs baseline: 1.7167x; 1.0031x over previous
#include <cuda_runtime.h>
#include <cuda_bf16.h>
#include <cstddef>
#include <cstdint>

#define EMB_E   300
#define HID     128
#define NT      12
#define SOS_T   3
#define EOS_T   4
#define NEGV    (-10000.0f)
#define BATCH   128
#define SEQ     512
#define G4H     512

#define KPRIME  960           /* 3*304 + 48 pad */
#define KCH     32
#define NCHK    30            /* 960/32 */
#define MROWS   65536         /* BATCH*SEQ */

// Scratch (device globals; no runtime allocation allowed)
// g_WX layout: [dir][b][s][u][gate]  (gate-interleaved, float4 per unit)
__device__ float g_WX[67108864];
__device__ float g_H [16777216];            // [dir][b][s][128]
__device__ __nv_bfloat16 g_Abf[62914560];   // [65536][960] split-bf16 A'
__device__ __nv_bfloat16 g_Bbf[983040];     // [1024][960]  split-bf16 B'

// ---- packed fp32 helpers (valid on plain sm_100) ----
__device__ __forceinline__ void ffma2(unsigned long long& d,
                                      unsigned long long a, unsigned long long b) {
    asm("fma.rn.f32x2 %0, %1, %2, %0;" : "+l"(d) : "l"(a), "l"(b));
}
__device__ __forceinline__ unsigned long long pk2(float lo, float hi) {
    unsigned long long r;
    asm("mov.b64 %0, {%1, %2};" : "=l"(r) : "f"(lo), "f"(hi));
    return r;
}
__device__ __forceinline__ void unpk(unsigned long long v, float& lo, float& hi) {
    asm("mov.b64 {%0, %1}, %2;" : "=f"(lo), "=f"(hi) : "l"(v));
}
__device__ __forceinline__ uint32_t smem_u32(const void* p) {
    uint32_t a;
    asm("{ .reg .u64 t; cvta.to.shared.u64 t, %1; cvt.u32.u64 %0, t; }"
        : "=r"(a) : "l"(p));
    return a;
}

// ---------------------------------------------------------------------------
// P1: build A' = [Ah | Ah | Al] per token row (gather from embed). warp/row.
// ---------------------------------------------------------------------------
__global__ void __launch_bounds__(256) prep_A_kernel(
    const int* __restrict__ x, const float* __restrict__ embed)
{
    const int w    = (blockIdx.x * 256 + threadIdx.x) >> 5;
    const int lane = threadIdx.x & 31;
    if (w >= MROWS) return;
    const float* src = embed + (size_t)x[w] * EMB_E;
    __nv_bfloat16* dst = g_Abf + (size_t)w * KPRIME;
    for (int k = lane; k < 304; k += 32) {
        float v = (k < 300) ? src[k] : 0.f;
        __nv_bfloat16 hi = __float2bfloat16(v);
        float lo = v - __bfloat162float(hi);
        dst[k]       = hi;
        dst[304 + k] = hi;
        dst[608 + k] = __float2bfloat16(lo);
    }
    if (lane < 48) dst[912 + lane] = __float2bfloat16(0.f);
}

// ---------------------------------------------------------------------------
// P2: build B' = [Bh | Bl | Bh] for both dirs (1024 rows). warp/row.
// ---------------------------------------------------------------------------
__global__ void __launch_bounds__(256) prep_B_kernel(
    const float* __restrict__ Wih_f, const float* __restrict__ Wih_b)
{
    const int w    = (blockIdx.x * 256 + threadIdx.x) >> 5;
    const int lane = threadIdx.x & 31;
    if (w >= 1024) return;
    const int dir = w >> 9, row = w & 511;
    const float* src = (dir ? Wih_b : Wih_f) + (size_t)row * EMB_E;
    __nv_bfloat16* dst = g_Bbf + (size_t)w * KPRIME;
    for (int k = lane; k < 304; k += 32) {
        float v = (k < 300) ? src[k] : 0.f;
        __nv_bfloat16 hi = __float2bfloat16(v);
        float lo = v - __bfloat162float(hi);
        dst[k]       = hi;
        dst[304 + k] = __float2bfloat16(lo);
        dst[608 + k] = hi;
    }
    if (lane < 48) dst[912 + lane] = __float2bfloat16(0.f);
}

// ---------------------------------------------------------------------------
// K1: bf16 mma.sync GEMM. Grid 4096 = 512 M x 8 N (N fast), 256 thr, 2 CTA/SM.
// Epilogue stores gate-interleaved layout for K2's single-LDG.128 wx fetch.
// ---------------------------------------------------------------------------
__global__ void __launch_bounds__(256, 2) mma_gemm_kernel(
    const float* __restrict__ b_f, const float* __restrict__ b_b)
{
    __shared__ __nv_bfloat16 As[2][128][40];
    __shared__ __nv_bfloat16 Bs[2][128][40];

    const int tid  = threadIdx.x;
    const int wid  = tid >> 5;
    const int lane = tid & 31;

    const int mt    = blockIdx.x >> 3;
    const int nt    = blockIdx.x & 7;
    const int m0    = mt * 128;
    const int dir   = nt >> 2;
    const int ncol0 = (nt & 3) * 128;
    const float* bsrc = dir ? b_b : b_f;

    const __nv_bfloat16* gA = g_Abf + (size_t)m0 * KPRIME;
    const __nv_bfloat16* gB = g_Bbf + ((size_t)dir * 512 + ncol0) * KPRIME;

    const int r0 = tid >> 2,            kq0 = tid & 3;
    const int r1 = (tid + 256) >> 2,    kq1 = (tid + 256) & 3;

    float4 pa0, pa1, pb0, pb1;
    {
        pa0 = *(const float4*)(gA + (size_t)r0 * KPRIME + kq0 * 8);
        pa1 = *(const float4*)(gA + (size_t)r1 * KPRIME + kq1 * 8);
        pb0 = *(const float4*)(gB + (size_t)r0 * KPRIME + kq0 * 8);
        pb1 = *(const float4*)(gB + (size_t)r1 * KPRIME + kq1 * 8);
        *(float4*)&As[0][r0][kq0 * 8] = pa0;
        *(float4*)&As[0][r1][kq1 * 8] = pa1;
        *(float4*)&Bs[0][r0][kq0 * 8] = pb0;
        *(float4*)&Bs[0][r1][kq1 * 8] = pb1;
    }
    __syncthreads();

    const int warp_m = wid >> 2;
    const int warp_n = wid & 3;

    float acc[4][4][4];
    #pragma unroll
    for (int i = 0; i < 4; i++)
        #pragma unroll
        for (int j = 0; j < 4; j++)
            #pragma unroll
            for (int q = 0; q < 4; q++) acc[i][j][q] = 0.f;

    for (int c = 0; c < NCHK; c++) {
        const int buf = c & 1;
        if (c + 1 < NCHK) {
            const int koff = (c + 1) * KCH;
            pa0 = *(const float4*)(gA + (size_t)r0 * KPRIME + koff + kq0 * 8);
            pa1 = *(const float4*)(gA + (size_t)r1 * KPRIME + koff + kq1 * 8);
            pb0 = *(const float4*)(gB + (size_t)r0 * KPRIME + koff + kq0 * 8);
            pb1 = *(const float4*)(gB + (size_t)r1 * KPRIME + koff + kq1 * 8);
        }

        #pragma unroll
        for (int ks = 0; ks < 2; ks++) {
            uint32_t a[4][4];
            #pragma unroll
            for (int mf = 0; mf < 4; mf++) {
                uint32_t addr = smem_u32(
                    &As[buf][warp_m * 64 + mf * 16 + (lane & 15)]
                           [ks * 16 + (lane >> 4) * 8]);
                asm volatile(
                    "ldmatrix.sync.aligned.m8n8.x4.shared.b16 {%0,%1,%2,%3}, [%4];"
                    : "=r"(a[mf][0]), "=r"(a[mf][1]), "=r"(a[mf][2]), "=r"(a[mf][3])
                    : "r"(addr));
            }
            #pragma unroll
            for (int nf = 0; nf < 4; nf++) {
                uint32_t b0, b1;
                uint32_t addr = smem_u32(
                    &Bs[buf][warp_n * 32 + nf * 8 + (lane & 7)]
                           [ks * 16 + ((lane >> 3) & 1) * 8]);
                asm volatile(
                    "ldmatrix.sync.aligned.m8n8.x2.shared.b16 {%0,%1}, [%2];"
                    : "=r"(b0), "=r"(b1) : "r"(addr));
                #pragma unroll
                for (int mf = 0; mf < 4; mf++) {
                    asm volatile(
                        "mma.sync.aligned.m16n8k16.row.col.f32.bf16.bf16.f32 "
                        "{%0,%1,%2,%3}, {%4,%5,%6,%7}, {%8,%9}, {%0,%1,%2,%3};"
                        : "+f"(acc[mf][nf][0]), "+f"(acc[mf][nf][1]),
                          "+f"(acc[mf][nf][2]), "+f"(acc[mf][nf][3])
                        : "r"(a[mf][0]), "r"(a[mf][1]), "r"(a[mf][2]), "r"(a[mf][3]),
                          "r"(b0), "r"(b1));
                }
            }
        }

        __syncthreads();
        if (c + 1 < NCHK) {
            const int nxt = buf ^ 1;
            *(float4*)&As[nxt][r0][kq0 * 8] = pa0;
            *(float4*)&As[nxt][r1][kq1 * 8] = pa1;
            *(float4*)&Bs[nxt][r0][kq0 * 8] = pb0;
            *(float4*)&Bs[nxt][r1][kq1 * 8] = pb1;
            __syncthreads();
        }
    }

    // epilogue: bias + store, gate-interleaved: off = (c&127)*4 + (c>>7)
    #pragma unroll
    for (int nf = 0; nf < 4; nf++) {
        const int col = ncol0 + warp_n * 32 + nf * 8 + (lane & 3) * 2;
        const float bx = __ldg(bsrc + col);
        const float by = __ldg(bsrc + col + 1);
        const int off0 = ((col & 127) << 2) + (col >> 7);
        const int off1 = (((col + 1) & 127) << 2) + ((col + 1) >> 7);
        #pragma unroll
        for (int mf = 0; mf < 4; mf++) {
            const int ra = m0 + warp_m * 64 + mf * 16 + (lane >> 2);
            #pragma unroll
            for (int h = 0; h < 2; h++) {
                const int row  = ra + h * 8;
                const int bidx = row >> 9;
                const int s    = row & 511;
                float* base = g_WX + (((size_t)dir * BATCH + bidx) * SEQ + s) * G4H;
                base[off0] = acc[mf][nf][2 * h]     + bx;
                base[off1] = acc[mf][nf][2 * h + 1] + by;
            }
        }
    }
}

// ---------------------------------------------------------------------------
// K2 v3: BiLSTM recurrence. 128 CTAs = 2 dirs x 64 batch-pairs, 256 threads.
// Thread (u, khalf): all 4 gate rows of unit u, both batches, over 64-k half.
// Weights: k-chunk 32/row in regs, 32/row in per-warp transposed smem.
// One barrier/step; ping-pong hsm; shfl-combined k-halves.
// ---------------------------------------------------------------------------
__global__ void __launch_bounds__(256) lstm_rec_kernel(
    const float* __restrict__ Whh_f, const float* __restrict__ Whh_b)
{
    extern __shared__ __align__(16) float sm2[];
    float* Wsm = sm2;                 // [8 warps][32 slots][32 lanes] float4 = 128KB
    float* hsm = sm2 + 32768;         // [2 bufs][2 batch][128] = 512 floats

    const int tid  = threadIdx.x;
    const int u    = tid >> 1;
    const int half = tid & 1;
    const int w    = tid >> 5;
    const int lane = tid & 31;
    const int dir  = blockIdx.x >> 6;
    const int b0   = (blockIdx.x & 63) * 2;
    const float* Whh = dir ? Whh_b : Whh_f;
    const int kbase = half * 64;

    // reg weights: rows u+128r, k in [kbase, kbase+32) -> 16 u64 pairs per row
    unsigned long long wreg[4][16];
    #pragma unroll
    for (int r = 0; r < 4; r++) {
        const float* row = Whh + (size_t)(u + 128 * r) * HID + kbase;
        #pragma unroll
        for (int q = 0; q < 8; q++) {
            float4 v = *(const float4*)(row + 4 * q);
            wreg[r][2 * q]     = pk2(v.x, v.y);
            wreg[r][2 * q + 1] = pk2(v.z, v.w);
        }
    }
    // smem weights: rows u+128r, k in [kbase+32, kbase+64): 8 float4 per row
    {
        float4* wsm4 = (float4*)Wsm;
        #pragma unroll
        for (int r = 0; r < 4; r++) {
            const float* row = Whh + (size_t)(u + 128 * r) * HID + kbase + 32;
            #pragma unroll
            for (int j = 0; j < 8; j++)
                wsm4[((w * 32 + r * 8 + j) << 5) + lane] = *(const float4*)(row + 4 * j);
        }
    }
    for (int i = tid; i < 512; i += 256) hsm[i] = 0.f;
    float cc = 0.f;
    __syncthreads();

    const float* wxbase = g_WX + ((size_t)dir * BATCH + b0 + half) * SEQ * (size_t)G4H;
    const int s0 = dir ? (SEQ - 1) : 0;
    float4 wx = __ldg((const float4*)(wxbase + (size_t)s0 * G4H + u * 4));

    const float4* wsm4r = (const float4*)Wsm + ((size_t)w << 10) + lane;

    for (int t = 0; t < SEQ; t++) {
        const int s = dir ? (SEQ - 1 - t) : t;
        const float4 cwx = wx;
        if (t < SEQ - 1) {
            const int sn = dir ? (SEQ - 2 - t) : (t + 1);
            wx = __ldg((const float4*)(wxbase + (size_t)sn * G4H + u * 4));
        }
        const float* hb = hsm + ((t & 1) << 8);

        unsigned long long acc[4][2];
        #pragma unroll
        for (int r = 0; r < 4; r++) { acc[r][0] = 0ULL; acc[r][1] = 0ULL; }

        // reg-weight part: k in [kbase, kbase+32)
        #pragma unroll
        for (int q = 0; q < 8; q++) {
            ulonglong2 hA = *(const ulonglong2*)(hb + kbase + 4 * q);
            ulonglong2 hB = *(const ulonglong2*)(hb + 128 + kbase + 4 * q);
            #pragma unroll
            for (int r = 0; r < 4; r++) {
                ffma2(acc[r][0], wreg[r][2 * q],     hA.x);
                ffma2(acc[r][0], wreg[r][2 * q + 1], hA.y);
                ffma2(acc[r][1], wreg[r][2 * q],     hB.x);
                ffma2(acc[r][1], wreg[r][2 * q + 1], hB.y);
            }
        }
        // smem-weight part: k in [kbase+32, kbase+64)
        #pragma unroll
        for (int j = 0; j < 8; j++) {
            ulonglong2 hA = *(const ulonglong2*)(hb + kbase + 32 + 4 * j);
            ulonglong2 hB = *(const ulonglong2*)(hb + 128 + kbase + 32 + 4 * j);
            #pragma unroll
            for (int r = 0; r < 4; r++) {
                ulonglong2 wv = *(const ulonglong2*)(wsm4r + (((r << 3) + j) << 5));
                ffma2(acc[r][0], wv.x, hA.x);
                ffma2(acc[r][0], wv.y, hA.y);
                ffma2(acc[r][1], wv.x, hB.x);
                ffma2(acc[r][1], wv.y, hB.y);
            }
        }

        // combine packed halves + k-half lane pair
        float d0[4], d1[4];
        #pragma unroll
        for (int r = 0; r < 4; r++) {
            float lo, hi;
            unpk(acc[r][0], lo, hi); d0[r] = lo + hi;
            unpk(acc[r][1], lo, hi); d1[r] = lo + hi;
        }
        #pragma unroll
        for (int r = 0; r < 4; r++) {
            d0[r] += __shfl_xor_sync(0xffffffffu, d0[r], 1);
            d1[r] += __shfl_xor_sync(0xffffffffu, d1[r], 1);
        }

        const float gi = (half ? d1[0] : d0[0]) + cwx.x;
        const float gf = (half ? d1[1] : d0[1]) + cwx.y;
        const float gg = (half ? d1[2] : d0[2]) + cwx.z;
        const float go = (half ? d1[3] : d0[3]) + cwx.w;

        float si = 1.f / (1.f + __expf(-gi));
        float sf = 1.f / (1.f + __expf(-gf));
        float so = 1.f / (1.f + __expf(-go));
        float ea = __expf(-2.f * fabsf(gg));
        float tg = (1.f - ea) / (1.f + ea); tg = (gg < 0.f) ? -tg : tg;
        cc = sf * cc + si * tg;
        float eb = __expf(-2.f * fabsf(cc));
        float tc = (1.f - eb) / (1.f + eb); tc = (cc < 0.f) ? -tc : tc;
        const float h = so * tc;

        hsm[(((t + 1) & 1) << 8) + (half << 7) + u] = h;
        g_H[(((size_t)dir * BATCH + b0 + half) * SEQ + s) * HID + u] = h;
        __syncthreads();
    }
}

// ---------------------------------------------------------------------------
// K3: emissions + CRF forward + gold score. 1 CTA per batch, 128 threads.
// ---------------------------------------------------------------------------
__global__ void __launch_bounds__(128) crf_kernel(
    const float* __restrict__ Wout, const float* __restrict__ bout,
    const float* __restrict__ trans, const int* __restrict__ y0,
    float* __restrict__ out)
{
    __shared__ float Wsm[NT * 256];
    __shared__ float bsm[NT];
    __shared__ float tsm[NT * NT];
    __shared__ float hsm[256];
    __shared__ float ysm[NT];
    __shared__ float score[2][NT];
    __shared__ float gold_s;
    __shared__ int   ysq[SEQ];

    const int tid = threadIdx.x;
    const int b   = blockIdx.x;
    for (int i = tid; i < NT * 256; i += 128) Wsm[i] = Wout[i];
    if (tid < NT) bsm[tid] = bout[tid];
    for (int i = tid; i < NT * NT; i += 128) tsm[i] = trans[i];
    if (tid < NT) score[0][tid] = (tid == SOS_T) ? 0.f : NEGV;
    for (int i = tid; i < SEQ; i += 128) ysq[i] = y0[b * SEQ + i];
    __syncthreads();

    const float* Hf = g_H + (size_t)b * SEQ * HID;
    const float* Hb = g_H + ((size_t)BATCH + b) * SEQ * HID;
    float hvf = Hf[tid], hvb = Hb[tid];
    const int wid = tid >> 5, lane = tid & 31;
    float gold = 0.f; int prev = SOS_T;
    int cur = 0;

    for (int s = 0; s < SEQ; s++) {
        hsm[tid] = hvf; hsm[128 + tid] = hvb;
        __syncthreads();
        if (s < SEQ - 1) { hvf = Hf[(s+1)*HID + tid]; hvb = Hb[(s+1)*HID + tid]; }
        #pragma unroll
        for (int tt = 0; tt < 3; tt++) {
            const int t = wid * 3 + tt;
            const float* wp = Wsm + t * 256 + lane * 8;
            const float* hp = hsm + lane * 8;
            float a = 0.f;
            #pragma unroll
            for (int q = 0; q < 8; q++) a += wp[q] * hp[q];
            #pragma unroll
            for (int o = 16; o > 0; o >>= 1) a += __shfl_xor_sync(0xffffffffu, a, o);
            if (lane == 0) ysm[t] = a + bsm[t];
        }
        __syncthreads();
        if (tid < NT) {
            float sc[NT], m = -1e30f;
            #pragma unroll
            for (int jj = 0; jj < NT; jj++) {
                float v = score[cur][jj] + tsm[tid * NT + jj];
                sc[jj] = v; m = fmaxf(m, v);
            }
            float sum = 0.f;
            #pragma unroll
            for (int jj = 0; jj < NT; jj++) sum += __expf(sc[jj] - m);
            score[cur ^ 1][tid] = m + __logf(sum) + ysm[tid];
        }
        if (tid == 64) {
            const int tag = ysq[s];
            gold += ysm[tag] + tsm[tag * NT + prev];
            prev = tag;
        }
        cur ^= 1;
        __syncthreads();
    }

    if (tid == 64) { gold += tsm[EOS_T * NT + prev]; gold_s = gold; }
    if (tid < NT) ysm[tid] = score[cur][tid] + tsm[EOS_T * NT + tid];
    __syncthreads();
    if (tid == 0) {
        float m = -1e30f;
        #pragma unroll
        for (int jj = 0; jj < NT; jj++) m = fmaxf(m, ysm[jj]);
        float sum = 0.f;
        #pragma unroll
        for (int jj = 0; jj < NT; jj++) sum += __expf(ysm[jj] - m);
        out[b] = m + __logf(sum) - gold_s;
    }
}

extern "C" void kernel_launch(void* const* d_in, const int* in_sizes, int n_in,
                              void* d_out, int out_size)
{
    const int*   x     = (const int*)  d_in[0];
    const int*   y0    = (const int*)  d_in[1];
    const float* embed = (const float*)d_in[2];
    const float* Wih_f = (const float*)d_in[3];
    const float* Whh_f = (const float*)d_in[4];
    const float* b_f   = (const float*)d_in[5];
    const float* Wih_b = (const float*)d_in[6];
    const float* Whh_b = (const float*)d_in[7];
    const float* b_b   = (const float*)d_in[8];
    const float* Wout  = (const float*)d_in[9];
    const float* bout  = (const float*)d_in[10];
    const float* trans = (const float*)d_in[11];

    const int smem2 = 32768 * 4 + 512 * 4;   // 128KB weights + hsm
    cudaFuncSetAttribute(lstm_rec_kernel,
        cudaFuncAttributeMaxDynamicSharedMemorySize, smem2);

    prep_A_kernel<<<MROWS / 8, 256>>>(x, embed);
    prep_B_kernel<<<128, 256>>>(Wih_f, Wih_b);
    mma_gemm_kernel<<<4096, 256>>>(b_f, b_b);
    lstm_rec_kernel<<<128, 256, smem2>>>(Whh_f, Whh_b);
    crf_kernel<<<BATCH, 128>>>(Wout, bout, trans, y0, (float*)d_out);
}